// round 2
// baseline (speedup 1.0000x reference)
#include <cuda_runtime.h>
#include <cuda_bf16.h>
#include <cstdint>

// Problem constants
#define NN   20000
#define EE   640000
#define F0   128
#define F1   256
#define F2   128
#define NPAD 20096   // 157 * 128

// ---------------- scratch (device globals; zero-initialized at module load) ----
__device__ __align__(16) float g_deg[NPAD];
__device__ __align__(16) float g_dis[NPAD];
__device__ __align__(16) float g_wn[EE];
__device__ __align__(16) float g_TxA[4 * NPAD * F0];   // layer1 Chebyshev stack
__device__ __align__(16) float g_out1[NPAD * F1];      // layer1 conv output
__device__ __align__(16) float g_TxB[4 * NPAD * F1];   // layer2 Chebyshev stack
__device__ __align__(16) float g_out2[NPAD * F2];      // layer2 conv output
__device__ __align__(16) float g_h2[NPAD * F2];        // post-BN2
__device__ __align__(16) float g_stats[2 * F1];        // per-column sum / sumsq
__device__ __align__(16) float g_scale[F1];
__device__ __align__(16) float g_shift[F1];

// ---------------- norm precompute ------------------------------------------
__global__ void deg_kernel(const int* __restrict__ row,
                           const int* __restrict__ col,
                           const float* __restrict__ ew) {
    int e = blockIdx.x * blockDim.x + threadIdx.x;
    if (e >= EE) return;
    int r = row[e], c = col[e];
    float w = (r == c) ? 0.f : ew[e];
    if (w != 0.f) atomicAdd(&g_deg[r], w);
}

__global__ void dis_kernel() {
    int i = blockIdx.x * blockDim.x + threadIdx.x;
    if (i >= NN) return;
    float d = g_deg[i];
    g_dis[i] = (d > 0.f) ? rsqrtf(d) : 0.f;
}

__global__ void wnorm_kernel(const int* __restrict__ row,
                             const int* __restrict__ col,
                             const float* __restrict__ ew) {
    int e = blockIdx.x * blockDim.x + threadIdx.x;
    if (e >= EE) return;
    int r = row[e], c = col[e];
    float w = (r == c) ? 0.f : ew[e];
    // w_norm = -(dis[r] * w * dis[c]) * (2/lambda_max), lambda_max = 2
    g_wn[e] = -g_dis[r] * w * g_dis[c];
}

// ---------------- SPMM: out[col] += scale * w_norm[e] * in[row] -------------
template <int F>
__global__ void spmm_kernel(const float* __restrict__ in, float* __restrict__ out,
                            const int* __restrict__ row,
                            const int* __restrict__ col,
                            float scale) {
    int warp = (blockIdx.x * blockDim.x + threadIdx.x) >> 5;
    int lane = threadIdx.x & 31;
    if (warp >= EE) return;
    float w = g_wn[warp] * scale;
    if (w == 0.f) return;
    int r = row[warp];
    int c = col[warp];
    const float4* src = (const float4*)(in + (size_t)r * F);
    float4*       dst = (float4*)(out + (size_t)c * F);
#pragma unroll
    for (int it = 0; it < F / 128; ++it) {
        float4 v = src[lane + it * 32];
        v.x *= w; v.y *= w; v.z *= w; v.w *= w;
        asm volatile("red.global.add.v4.f32 [%0], {%1, %2, %3, %4};"
                     :: "l"(dst + lane + it * 32),
                        "f"(v.x), "f"(v.y), "f"(v.z), "f"(v.w)
                     : "memory");
    }
}

// a[i] -= b[i]  (float4 granularity)
__global__ void sub_kernel(float* __restrict__ a, const float* __restrict__ b, int n4) {
    int i = blockIdx.x * blockDim.x + threadIdx.x;
    if (i >= n4) return;
    float4 va = ((float4*)a)[i];
    float4 vb = ((const float4*)b)[i];
    va.x -= vb.x; va.y -= vb.y; va.z -= vb.z; va.w -= vb.w;
    ((float4*)a)[i] = va;
}

// ---------------- fused 4-chunk SGEMM: C = sum_k A_k @ W_k + bias -----------
// A: [4][NPAD][FIN] (row padded), W: [4][FIN][FOUTT], C: [NPAD][FOUTT]
template <int FIN, int FOUTT>
__global__ __launch_bounds__(256)
void gemm_kernel(const float* __restrict__ A, const float* __restrict__ W,
                 const float* __restrict__ bias, float* __restrict__ C) {
    const int BM = 128, BN = 128, BK = 16;
    __shared__ float As[BK][BM + 4];
    __shared__ float Bs[BK][BN];
    int tid = threadIdx.x;
    int tx = tid & 15;        // 0..15 -> col groups of 8
    int ty = tid >> 4;        // 0..15 -> row groups of 8
    int bm = blockIdx.x * BM;
    int bn = blockIdx.y * BN;

    float acc[8][8];
#pragma unroll
    for (int i = 0; i < 8; i++)
#pragma unroll
        for (int j = 0; j < 8; j++) acc[i][j] = 0.f;

#pragma unroll 1
    for (int chunk = 0; chunk < 4; ++chunk) {
        const float* Ab = A + (size_t)chunk * NPAD * FIN;
        const float* Wb = W + (size_t)chunk * FIN * FOUTT;
#pragma unroll 1
        for (int k0 = 0; k0 < FIN; k0 += BK) {
            // A tile: BM x BK, stored transposed into As
#pragma unroll
            for (int p = 0; p < 2; ++p) {
                int idx = p * 256 + tid;     // 0..511
                int ar = idx >> 2;           // 0..127
                int ac = (idx & 3) * 4;      // 0,4,8,12
                float4 v = *(const float4*)(Ab + (size_t)(bm + ar) * FIN + k0 + ac);
                As[ac + 0][ar] = v.x;
                As[ac + 1][ar] = v.y;
                As[ac + 2][ar] = v.z;
                As[ac + 3][ar] = v.w;
            }
            // B tile: BK x BN
#pragma unroll
            for (int p = 0; p < 2; ++p) {
                int idx = p * 256 + tid;
                int br = idx >> 5;           // 0..15
                int bc = (idx & 31) * 4;     // 0..124
                float4 v = *(const float4*)(Wb + (size_t)(k0 + br) * FOUTT + bn + bc);
                *(float4*)&Bs[br][bc] = v;
            }
            __syncthreads();
#pragma unroll
            for (int kk = 0; kk < BK; ++kk) {
                float ra[8], rb[8];
                float4 a0 = *(const float4*)&As[kk][ty * 8];
                float4 a1 = *(const float4*)&As[kk][ty * 8 + 4];
                ra[0]=a0.x; ra[1]=a0.y; ra[2]=a0.z; ra[3]=a0.w;
                ra[4]=a1.x; ra[5]=a1.y; ra[6]=a1.z; ra[7]=a1.w;
                float4 b0 = *(const float4*)&Bs[kk][tx * 8];
                float4 b1 = *(const float4*)&Bs[kk][tx * 8 + 4];
                rb[0]=b0.x; rb[1]=b0.y; rb[2]=b0.z; rb[3]=b0.w;
                rb[4]=b1.x; rb[5]=b1.y; rb[6]=b1.z; rb[7]=b1.w;
#pragma unroll
                for (int i = 0; i < 8; i++)
#pragma unroll
                    for (int j = 0; j < 8; j++)
                        acc[i][j] = fmaf(ra[i], rb[j], acc[i][j]);
            }
            __syncthreads();
        }
    }
    // store with bias (rows are padded; no guards needed)
#pragma unroll
    for (int i = 0; i < 8; i++) {
        int r = bm + ty * 8 + i;
#pragma unroll
        for (int j = 0; j < 8; j += 4) {
            int cc = bn + tx * 8 + j;
            float4 v;
            v.x = acc[i][j + 0] + bias[cc + 0];
            v.y = acc[i][j + 1] + bias[cc + 1];
            v.z = acc[i][j + 2] + bias[cc + 2];
            v.w = acc[i][j + 3] + bias[cc + 3];
            *(float4*)(C + (size_t)r * FOUTT + cc) = v;
        }
    }
}

// ---------------- BN (training mode) over node axis, relu fused into stats --
template <int F>
__global__ void stats_kernel(const float* __restrict__ X) {
    int col = threadIdx.x & (F - 1);
    int ro = threadIdx.x / F;
    int rstep = 256 / F;
    int r0 = blockIdx.x * 128 + ro;
    int rend = blockIdx.x * 128 + 128;
    if (rend > NN) rend = NN;
    float s = 0.f, s2 = 0.f;
    for (int r = r0; r < rend; r += rstep) {
        float v = X[(size_t)r * F + col];
        v = v > 0.f ? v : 0.f;
        s += v;
        s2 = fmaf(v, v, s2);
    }
    atomicAdd(&g_stats[col], s);
    atomicAdd(&g_stats[F + col], s2);
}

__global__ void scaleshift_kernel(const float* __restrict__ gamma,
                                  const float* __restrict__ beta, int F) {
    int c = threadIdx.x;
    if (c >= F) return;
    float m = g_stats[c] / (float)NN;
    float v = g_stats[F + c] / (float)NN - m * m;
    float inv = rsqrtf(v + 1e-5f);
    float sc = gamma[c] * inv;
    g_scale[c] = sc;
    g_shift[c] = beta[c] - m * sc;
}

template <int F>
__global__ void bnapply_kernel(const float* __restrict__ x, float* __restrict__ y, int n) {
    int i = blockIdx.x * blockDim.x + threadIdx.x;
    if (i >= n) return;
    int c = i & (F - 1);
    float v = x[i];
    v = v > 0.f ? v : 0.f;
    y[i] = fmaf(v, g_scale[c], g_shift[c]);
}

// ---------------- final linear: out = h2 @ Wlin^T + blin --------------------
__global__ void final_kernel(const float* __restrict__ h, const float* __restrict__ Wl,
                             const float* __restrict__ bl, float* __restrict__ out) {
    int idx = blockIdx.x * blockDim.x + threadIdx.x;
    int n = idx >> 4;
    int o = idx & 15;
    if (n >= NN || o >= 10) return;
    const float* hr = h + (size_t)n * F2;
    const float* wr = Wl + o * F2;
    float s = bl[o];
#pragma unroll 8
    for (int c = 0; c < F2; ++c) s = fmaf(hr[c], wr[c], s);
    out[n * 10 + o] = s;
}

// ---------------- launch ----------------------------------------------------
extern "C" void kernel_launch(void* const* d_in, const int* in_sizes, int n_in,
                              void* d_out, int out_size) {
    const float* x      = (const float*)d_in[0];
    const int*   ei     = (const int*)d_in[1];     // int32! (JAX x64 disabled)
    const float* ew     = (const float*)d_in[2];
    const float* W1     = (const float*)d_in[3];
    const float* b1     = (const float*)d_in[4];
    const float* W2     = (const float*)d_in[5];
    const float* b2     = (const float*)d_in[6];
    const float* gamma1 = (const float*)d_in[7];
    const float* beta1  = (const float*)d_in[8];
    const float* gamma2 = (const float*)d_in[9];
    const float* beta2  = (const float*)d_in[10];
    const float* Wlin   = (const float*)d_in[11];
    const float* blin   = (const float*)d_in[12];
    float* out = (float*)d_out;

    const int* row = ei;
    const int* col = ei + EE;

    float *deg, *TxA, *TxB, *out1, *out2, *h2, *stats;
    cudaGetSymbolAddress((void**)&deg,   g_deg);
    cudaGetSymbolAddress((void**)&TxA,   g_TxA);
    cudaGetSymbolAddress((void**)&TxB,   g_TxB);
    cudaGetSymbolAddress((void**)&out1,  g_out1);
    cudaGetSymbolAddress((void**)&out2,  g_out2);
    cudaGetSymbolAddress((void**)&h2,    g_h2);
    cudaGetSymbolAddress((void**)&stats, g_stats);

    const int EB = (EE + 255) / 256;      // edge-parallel blocks
    const int SPMMB = EE / 8;             // 8 warps (edges) per block

    // ---- normalization precompute ----
    cudaMemsetAsync(deg, 0, NPAD * sizeof(float));
    deg_kernel<<<EB, 256>>>(row, col, ew);
    dis_kernel<<<(NN + 255) / 256, 256>>>();
    wnorm_kernel<<<EB, 256>>>(row, col, ew);

    // ---- zero scatter targets (atomics accumulate; must re-zero per replay)
    cudaMemsetAsync(TxA + (size_t)NPAD * F0, 0, (size_t)3 * NPAD * F0 * sizeof(float));
    cudaMemsetAsync(TxB + (size_t)NPAD * F1, 0, (size_t)3 * NPAD * F1 * sizeof(float));
    cudaMemsetAsync(stats, 0, 2 * F1 * sizeof(float));

    // Tx0 = x (padding rows of block 0 stay zero from static init)
    cudaMemcpyAsync(TxA, x, (size_t)NN * F0 * sizeof(float), cudaMemcpyDeviceToDevice);

    // ---- layer 1: Chebyshev stack ----
    float* A0 = TxA;
    float* A1 = TxA + (size_t)NPAD * F0;
    float* A2 = TxA + (size_t)2 * NPAD * F0;
    float* A3 = TxA + (size_t)3 * NPAD * F0;
    spmm_kernel<F0><<<SPMMB, 256>>>(A0, A1, row, col, 1.f);
    spmm_kernel<F0><<<SPMMB, 256>>>(A1, A2, row, col, 2.f);
    sub_kernel<<<(NN * F0 / 4 + 255) / 256, 256>>>(A2, A0, NN * F0 / 4);
    spmm_kernel<F0><<<SPMMB, 256>>>(A2, A3, row, col, 2.f);
    sub_kernel<<<(NN * F0 / 4 + 255) / 256, 256>>>(A3, A1, NN * F0 / 4);

    gemm_kernel<F0, F1><<<dim3(NPAD / 128, F1 / 128), 256>>>(TxA, W1, b1, out1);

    stats_kernel<F1><<<157, 256>>>(out1);
    scaleshift_kernel<<<1, 256>>>(gamma1, beta1, F1);
    // BN1 output goes directly into layer2's Tx block 0
    bnapply_kernel<F1><<<(NN * F1 + 255) / 256, 256>>>(out1, TxB, NN * F1);

    // ---- layer 2 ----
    float* B0 = TxB;
    float* B1 = TxB + (size_t)NPAD * F1;
    float* B2 = TxB + (size_t)2 * NPAD * F1;
    float* B3 = TxB + (size_t)3 * NPAD * F1;
    spmm_kernel<F1><<<SPMMB, 256>>>(B0, B1, row, col, 1.f);
    spmm_kernel<F1><<<SPMMB, 256>>>(B1, B2, row, col, 2.f);
    sub_kernel<<<(NN * F1 / 4 + 255) / 256, 256>>>(B2, B0, NN * F1 / 4);
    spmm_kernel<F1><<<SPMMB, 256>>>(B2, B3, row, col, 2.f);
    sub_kernel<<<(NN * F1 / 4 + 255) / 256, 256>>>(B3, B1, NN * F1 / 4);

    gemm_kernel<F1, F2><<<dim3(NPAD / 128, F2 / 128), 256>>>(TxB, W2, b2, out2);

    cudaMemsetAsync(stats, 0, 2 * F1 * sizeof(float));
    stats_kernel<F2><<<157, 256>>>(out2);
    scaleshift_kernel<<<1, 128>>>(gamma2, beta2, F2);
    bnapply_kernel<F2><<<(NN * F2 + 255) / 256, 256>>>(out2, h2, NN * F2);

    // ---- final linear ----
    final_kernel<<<(NN * 16 + 255) / 256, 256>>>(h2, Wlin, blin, out);
}

// round 3
// speedup vs baseline: 1.5377x; 1.5377x over previous
#include <cuda_runtime.h>
#include <cuda_bf16.h>
#include <cstdint>

// Problem constants
#define NN   20000
#define EE   640000
#define F0   128
#define F1   256
#define F2   128
#define NPAD 20096   // 157 * 128

// ---------------- scratch (device globals) ----------------------------------
__device__ __align__(16) float g_deg[NPAD];
__device__ __align__(16) float g_wn[EE];
__device__ __align__(16) int   g_cnt[NPAD];      // per-dst edge counts
__device__ __align__(16) int   g_cur[NPAD];      // scatter cursors
__device__ __align__(16) int   g_off[NN + 1];    // CSR offsets (by dst)
__device__ __align__(16) int2  g_pack[EE];       // (src_row, w_norm bits) sorted by dst
__device__ __align__(16) float g_TxA[4 * NPAD * F0];   // layer1 Chebyshev stack
__device__ __align__(16) float g_out1[NPAD * F1];
__device__ __align__(16) float g_TxB[4 * NPAD * F1];   // layer2 Chebyshev stack
__device__ __align__(16) float g_out2[NPAD * F2];
__device__ __align__(16) float g_h2[NPAD * F2];
__device__ __align__(16) float g_stats[2 * F1];
__device__ __align__(16) float g_scale[F1];
__device__ __align__(16) float g_shift[F1];

// ---------------- norm precompute + CSR build -------------------------------
// degree accumulation + per-destination edge counts (fused)
__global__ void deg_cnt_kernel(const int* __restrict__ row,
                               const int* __restrict__ col,
                               const float* __restrict__ ew) {
    int e = blockIdx.x * blockDim.x + threadIdx.x;
    if (e >= EE) return;
    int r = row[e], c = col[e];
    float w = (r == c) ? 0.f : ew[e];
    if (w != 0.f) atomicAdd(&g_deg[r], w);
    atomicAdd(&g_cnt[c], 1);
}

// dis + w_norm (two passes fused: need all degrees first -> separate kernels)
__global__ void dis_kernel() {
    int i = blockIdx.x * blockDim.x + threadIdx.x;
    if (i >= NN) return;
    float d = g_deg[i];
    g_deg[i] = (d > 0.f) ? rsqrtf(d) : 0.f;   // reuse g_deg as dis
}

__global__ void wnorm_kernel(const int* __restrict__ row,
                             const int* __restrict__ col,
                             const float* __restrict__ ew) {
    int e = blockIdx.x * blockDim.x + threadIdx.x;
    if (e >= EE) return;
    int r = row[e], c = col[e];
    float w = (r == c) ? 0.f : ew[e];
    g_wn[e] = -g_deg[r] * w * g_deg[c];   // lambda_max = 2 -> factor 1
}

// single-block exclusive prefix scan over g_cnt -> g_off
__global__ void scan_kernel() {
    __shared__ int sh[1024];
    __shared__ int carry;
    int tid = threadIdx.x;
    if (tid == 0) carry = 0;
    __syncthreads();
    for (int base = 0; base < NN; base += 1024) {
        int i = base + tid;
        int v = (i < NN) ? g_cnt[i] : 0;
        sh[tid] = v;
        __syncthreads();
#pragma unroll
        for (int o = 1; o < 1024; o <<= 1) {
            int t = (tid >= o) ? sh[tid - o] : 0;
            __syncthreads();
            sh[tid] += t;
            __syncthreads();
        }
        if (i < NN) g_off[i] = carry + sh[tid] - v;
        int total = sh[1023];
        __syncthreads();
        if (tid == 0) carry += total;
        __syncthreads();
    }
    if (tid == 0) g_off[NN] = carry;
}

__global__ void scatter_kernel(const int* __restrict__ row,
                               const int* __restrict__ col) {
    int e = blockIdx.x * blockDim.x + threadIdx.x;
    if (e >= EE) return;
    int c = col[e];
    int pos = atomicAdd(&g_cur[c], 1);
    int2 p;
    p.x = row[e];
    p.y = __float_as_int(g_wn[e]);
    g_pack[g_off[c] + pos] = p;
}

// ---------------- gather SPMM: out[n] = alpha * sum_e w*in[src] (- prev[n]) --
template <int F>
__global__ void spmm_gather(const float* __restrict__ in, float* __restrict__ out,
                            const float* __restrict__ prev, float alpha) {
    constexpr int WPN = F / 128;           // warps per node
    int gw = (blockIdx.x * blockDim.x + threadIdx.x) >> 5;
    int node = gw / WPN;
    int fc = gw % WPN;
    if (node >= NN) return;
    int lane = threadIdx.x & 31;
    int beg = g_off[node], end = g_off[node + 1];

    const float4* base = (const float4*)in + fc * 32 + lane;
    float4 acc0 = make_float4(0.f, 0.f, 0.f, 0.f);
    float4 acc1 = make_float4(0.f, 0.f, 0.f, 0.f);

    int i = beg;
    for (; i + 2 <= end; i += 2) {
        int2 p0 = g_pack[i];
        int2 p1 = g_pack[i + 1];
        float w0 = __int_as_float(p0.y);
        float w1 = __int_as_float(p1.y);
        float4 v0 = base[(size_t)p0.x * (F / 4)];
        float4 v1 = base[(size_t)p1.x * (F / 4)];
        acc0.x = fmaf(w0, v0.x, acc0.x); acc0.y = fmaf(w0, v0.y, acc0.y);
        acc0.z = fmaf(w0, v0.z, acc0.z); acc0.w = fmaf(w0, v0.w, acc0.w);
        acc1.x = fmaf(w1, v1.x, acc1.x); acc1.y = fmaf(w1, v1.y, acc1.y);
        acc1.z = fmaf(w1, v1.z, acc1.z); acc1.w = fmaf(w1, v1.w, acc1.w);
    }
    if (i < end) {
        int2 p0 = g_pack[i];
        float w0 = __int_as_float(p0.y);
        float4 v0 = base[(size_t)p0.x * (F / 4)];
        acc0.x = fmaf(w0, v0.x, acc0.x); acc0.y = fmaf(w0, v0.y, acc0.y);
        acc0.z = fmaf(w0, v0.z, acc0.z); acc0.w = fmaf(w0, v0.w, acc0.w);
    }
    float4 r;
    r.x = alpha * (acc0.x + acc1.x);
    r.y = alpha * (acc0.y + acc1.y);
    r.z = alpha * (acc0.z + acc1.z);
    r.w = alpha * (acc0.w + acc1.w);
    size_t oidx = (size_t)node * (F / 4) + fc * 32 + lane;
    if (prev) {
        float4 pv = ((const float4*)prev)[oidx];
        r.x -= pv.x; r.y -= pv.y; r.z -= pv.z; r.w -= pv.w;
    }
    ((float4*)out)[oidx] = r;
}

// ---------------- fused 4-chunk SGEMM: C = sum_k A_k @ W_k + bias -----------
template <int FIN, int FOUTT>
__global__ __launch_bounds__(256)
void gemm_kernel(const float* __restrict__ A, const float* __restrict__ W,
                 const float* __restrict__ bias, float* __restrict__ C) {
    const int BM = 128, BN = 128, BK = 16;
    __shared__ float As[BK][BM + 4];
    __shared__ float Bs[BK][BN];
    int tid = threadIdx.x;
    int tx = tid & 15;
    int ty = tid >> 4;
    int bm = blockIdx.x * BM;
    int bn = blockIdx.y * BN;

    float acc[8][8];
#pragma unroll
    for (int i = 0; i < 8; i++)
#pragma unroll
        for (int j = 0; j < 8; j++) acc[i][j] = 0.f;

#pragma unroll 1
    for (int chunk = 0; chunk < 4; ++chunk) {
        const float* Ab = A + (size_t)chunk * NPAD * FIN;
        const float* Wb = W + (size_t)chunk * FIN * FOUTT;
#pragma unroll 1
        for (int k0 = 0; k0 < FIN; k0 += BK) {
#pragma unroll
            for (int p = 0; p < 2; ++p) {
                int idx = p * 256 + tid;
                int ar = idx >> 2;
                int ac = (idx & 3) * 4;
                float4 v = *(const float4*)(Ab + (size_t)(bm + ar) * FIN + k0 + ac);
                As[ac + 0][ar] = v.x;
                As[ac + 1][ar] = v.y;
                As[ac + 2][ar] = v.z;
                As[ac + 3][ar] = v.w;
            }
#pragma unroll
            for (int p = 0; p < 2; ++p) {
                int idx = p * 256 + tid;
                int br = idx >> 5;
                int bc = (idx & 31) * 4;
                float4 v = *(const float4*)(Wb + (size_t)(k0 + br) * FOUTT + bn + bc);
                *(float4*)&Bs[br][bc] = v;
            }
            __syncthreads();
#pragma unroll
            for (int kk = 0; kk < BK; ++kk) {
                float ra[8], rb[8];
                float4 a0 = *(const float4*)&As[kk][ty * 8];
                float4 a1 = *(const float4*)&As[kk][ty * 8 + 4];
                ra[0]=a0.x; ra[1]=a0.y; ra[2]=a0.z; ra[3]=a0.w;
                ra[4]=a1.x; ra[5]=a1.y; ra[6]=a1.z; ra[7]=a1.w;
                float4 b0 = *(const float4*)&Bs[kk][tx * 8];
                float4 b1 = *(const float4*)&Bs[kk][tx * 8 + 4];
                rb[0]=b0.x; rb[1]=b0.y; rb[2]=b0.z; rb[3]=b0.w;
                rb[4]=b1.x; rb[5]=b1.y; rb[6]=b1.z; rb[7]=b1.w;
#pragma unroll
                for (int i = 0; i < 8; i++)
#pragma unroll
                    for (int j = 0; j < 8; j++)
                        acc[i][j] = fmaf(ra[i], rb[j], acc[i][j]);
            }
            __syncthreads();
        }
    }
#pragma unroll
    for (int i = 0; i < 8; i++) {
        int r = bm + ty * 8 + i;
#pragma unroll
        for (int j = 0; j < 8; j += 4) {
            int cc = bn + tx * 8 + j;
            float4 v;
            v.x = acc[i][j + 0] + bias[cc + 0];
            v.y = acc[i][j + 1] + bias[cc + 1];
            v.z = acc[i][j + 2] + bias[cc + 2];
            v.w = acc[i][j + 3] + bias[cc + 3];
            *(float4*)(C + (size_t)r * FOUTT + cc) = v;
        }
    }
}

// ---------------- BN (training) over node axis, relu fused ------------------
template <int F>
__global__ void stats_kernel(const float* __restrict__ X) {
    int col = threadIdx.x & (F - 1);
    int ro = threadIdx.x / F;
    int rstep = 256 / F;
    int r0 = blockIdx.x * 128 + ro;
    int rend = blockIdx.x * 128 + 128;
    if (rend > NN) rend = NN;
    float s = 0.f, s2 = 0.f;
    for (int r = r0; r < rend; r += rstep) {
        float v = X[(size_t)r * F + col];
        v = v > 0.f ? v : 0.f;
        s += v;
        s2 = fmaf(v, v, s2);
    }
    atomicAdd(&g_stats[col], s);
    atomicAdd(&g_stats[F + col], s2);
}

__global__ void scaleshift_kernel(const float* __restrict__ gamma,
                                  const float* __restrict__ beta, int F) {
    int c = threadIdx.x;
    if (c >= F) return;
    float m = g_stats[c] / (float)NN;
    float v = g_stats[F + c] / (float)NN - m * m;
    float inv = rsqrtf(v + 1e-5f);
    float sc = gamma[c] * inv;
    g_scale[c] = sc;
    g_shift[c] = beta[c] - m * sc;
}

template <int F>
__global__ void bnapply_kernel(const float* __restrict__ x, float* __restrict__ y, int n) {
    int i = blockIdx.x * blockDim.x + threadIdx.x;
    if (i >= n) return;
    int c = i & (F - 1);
    float v = x[i];
    v = v > 0.f ? v : 0.f;
    y[i] = fmaf(v, g_scale[c], g_shift[c]);
}

// ---------------- final linear: out = h2 @ Wlin^T + blin --------------------
__global__ void final_kernel(const float* __restrict__ h, const float* __restrict__ Wl,
                             const float* __restrict__ bl, float* __restrict__ out) {
    int idx = blockIdx.x * blockDim.x + threadIdx.x;
    int n = idx >> 4;
    int o = idx & 15;
    if (n >= NN || o >= 10) return;
    const float* hr = h + (size_t)n * F2;
    const float* wr = Wl + o * F2;
    float s = bl[o];
#pragma unroll 8
    for (int c = 0; c < F2; ++c) s = fmaf(hr[c], wr[c], s);
    out[n * 10 + o] = s;
}

// ---------------- launch ----------------------------------------------------
extern "C" void kernel_launch(void* const* d_in, const int* in_sizes, int n_in,
                              void* d_out, int out_size) {
    const float* x      = (const float*)d_in[0];
    const int*   ei     = (const int*)d_in[1];     // int32 (JAX x64 disabled)
    const float* ew     = (const float*)d_in[2];
    const float* W1     = (const float*)d_in[3];
    const float* b1     = (const float*)d_in[4];
    const float* W2     = (const float*)d_in[5];
    const float* b2     = (const float*)d_in[6];
    const float* gamma1 = (const float*)d_in[7];
    const float* beta1  = (const float*)d_in[8];
    const float* gamma2 = (const float*)d_in[9];
    const float* beta2  = (const float*)d_in[10];
    const float* Wlin   = (const float*)d_in[11];
    const float* blin   = (const float*)d_in[12];
    float* out = (float*)d_out;

    const int* row = ei;
    const int* col = ei + EE;

    float *deg, *TxA, *TxB, *out1, *out2, *h2, *stats;
    int *cnt, *cur;
    cudaGetSymbolAddress((void**)&deg,   g_deg);
    cudaGetSymbolAddress((void**)&cnt,   g_cnt);
    cudaGetSymbolAddress((void**)&cur,   g_cur);
    cudaGetSymbolAddress((void**)&TxA,   g_TxA);
    cudaGetSymbolAddress((void**)&TxB,   g_TxB);
    cudaGetSymbolAddress((void**)&out1,  g_out1);
    cudaGetSymbolAddress((void**)&out2,  g_out2);
    cudaGetSymbolAddress((void**)&h2,    g_h2);
    cudaGetSymbolAddress((void**)&stats, g_stats);

    const int EB = (EE + 255) / 256;

    // ---- normalization + CSR build (per replay; atomics require re-zero) ----
    cudaMemsetAsync(deg, 0, NPAD * sizeof(float));
    cudaMemsetAsync(cnt, 0, NPAD * sizeof(int));
    cudaMemsetAsync(cur, 0, NPAD * sizeof(int));
    cudaMemsetAsync(stats, 0, 2 * F1 * sizeof(float));

    deg_cnt_kernel<<<EB, 256>>>(row, col, ew);
    dis_kernel<<<(NN + 255) / 256, 256>>>();
    wnorm_kernel<<<EB, 256>>>(row, col, ew);
    scan_kernel<<<1, 1024>>>();
    scatter_kernel<<<EB, 256>>>(row, col);

    // Tx0 = x (padding rows of block 0 stay zero from static init)
    cudaMemcpyAsync(TxA, x, (size_t)NN * F0 * sizeof(float), cudaMemcpyDeviceToDevice);

    // ---- layer 1: Chebyshev stack (gather SPMM, recursion fused) ----
    float* A0 = TxA;
    float* A1 = TxA + (size_t)NPAD * F0;
    float* A2 = TxA + (size_t)2 * NPAD * F0;
    float* A3 = TxA + (size_t)3 * NPAD * F0;
    const int GB0 = (NN * (F0 / 128) * 32 + 255) / 256;
    spmm_gather<F0><<<GB0, 256>>>(A0, A1, nullptr, 1.f);
    spmm_gather<F0><<<GB0, 256>>>(A1, A2, A0, 2.f);
    spmm_gather<F0><<<GB0, 256>>>(A2, A3, A1, 2.f);

    gemm_kernel<F0, F1><<<dim3(NPAD / 128, F1 / 128), 256>>>(TxA, W1, b1, out1);

    stats_kernel<F1><<<157, 256>>>(out1);
    scaleshift_kernel<<<1, 256>>>(gamma1, beta1, F1);
    bnapply_kernel<F1><<<(NN * F1 + 255) / 256, 256>>>(out1, TxB, NN * F1);

    // ---- layer 2 ----
    float* B0 = TxB;
    float* B1 = TxB + (size_t)NPAD * F1;
    float* B2 = TxB + (size_t)2 * NPAD * F1;
    float* B3 = TxB + (size_t)3 * NPAD * F1;
    const int GB1 = (NN * (F1 / 128) * 32 + 255) / 256;
    spmm_gather<F1><<<GB1, 256>>>(B0, B1, nullptr, 1.f);
    spmm_gather<F1><<<GB1, 256>>>(B1, B2, B0, 2.f);
    spmm_gather<F1><<<GB1, 256>>>(B2, B3, B1, 2.f);

    gemm_kernel<F1, F2><<<dim3(NPAD / 128, F2 / 128), 256>>>(TxB, W2, b2, out2);

    cudaMemsetAsync(stats, 0, 2 * F1 * sizeof(float));
    stats_kernel<F2><<<157, 256>>>(out2);
    scaleshift_kernel<<<1, 128>>>(gamma2, beta2, F2);
    bnapply_kernel<F2><<<(NN * F2 + 255) / 256, 256>>>(out2, h2, NN * F2);

    // ---- final linear ----
    final_kernel<<<(NN * 16 + 255) / 256, 256>>>(h2, Wlin, blin, out);
}

// round 4
// speedup vs baseline: 2.3561x; 1.5322x over previous
#include <cuda_runtime.h>
#include <cuda_bf16.h>
#include <cstdint>

// Problem constants
#define NN   20000
#define EE   640000
#define F0   128
#define F1   256
#define F2   128
#define NPAD 20096   // 157 * 128

// ---------------- scratch (device globals) ----------------------------------
__device__ __align__(16) float g_deg[NPAD];
__device__ __align__(16) int   g_cnt[NPAD];      // per-dst edge counts
__device__ __align__(16) int   g_cur[NPAD];      // scatter cursors
__device__ __align__(16) int   g_off[NN + 1];    // CSR offsets (by dst)
__device__ __align__(16) int2  g_pack[EE];       // (src_row, w_norm bits) by dst
__device__ __align__(16) float g_TxA[4 * NPAD * F0];
__device__ __align__(16) float g_out1[NPAD * F1];
__device__ __align__(16) float g_TxB[4 * NPAD * F1];
__device__ __align__(16) float g_out2[NPAD * F2];
__device__ __align__(16) float g_h2[NPAD * F2];
__device__ __align__(16) float g_stats[2 * F1];
__device__ __align__(16) float g_scale[F1];
__device__ __align__(16) float g_shift[F1];

// ---------------- norm precompute + CSR build -------------------------------
__global__ void deg_cnt_kernel(const int* __restrict__ row,
                               const int* __restrict__ col,
                               const float* __restrict__ ew) {
    int e = blockIdx.x * blockDim.x + threadIdx.x;
    if (e >= EE) return;
    int r = row[e], c = col[e];
    float w = (r == c) ? 0.f : ew[e];
    if (w != 0.f) atomicAdd(&g_deg[r], w);
    atomicAdd(&g_cnt[c], 1);
}

__global__ void dis_kernel() {
    int i = blockIdx.x * blockDim.x + threadIdx.x;
    if (i >= NN) return;
    float d = g_deg[i];
    g_deg[i] = (d > 0.f) ? rsqrtf(d) : 0.f;   // g_deg now holds dis
}

// fast two-level scan: 1024 threads x 20 sequential elements
__global__ void scan_kernel() {
    const int PER = 20;   // 1024*20 = 20480 >= NN+1
    int tid = threadIdx.x;
    int base = tid * PER;
    int v[PER];
    int s = 0;
#pragma unroll
    for (int j = 0; j < PER; j++) {
        int idx = base + j;
        int t = (idx < NN) ? g_cnt[idx] : 0;
        v[j] = t;
        s += t;
    }
    int lane = tid & 31, warp = tid >> 5;
    // inclusive warp scan of s
    int p = s;
#pragma unroll
    for (int o = 1; o < 32; o <<= 1) {
        int t = __shfl_up_sync(0xffffffffu, p, o);
        if (lane >= o) p += t;
    }
    __shared__ int wsum[32];
    if (lane == 31) wsum[warp] = p;
    __syncthreads();
    if (warp == 0) {
        int q = wsum[lane];
#pragma unroll
        for (int o = 1; o < 32; o <<= 1) {
            int t = __shfl_up_sync(0xffffffffu, q, o);
            if (lane >= o) q += t;
        }
        wsum[lane] = q;
    }
    __syncthreads();
    int run = p - s + (warp ? wsum[warp - 1] : 0);   // exclusive prefix
#pragma unroll
    for (int j = 0; j < PER; j++) {
        int idx = base + j;
        if (idx <= NN) g_off[idx] = run;
        run += v[j];
    }
}

// scatter with fused w_norm computation
__global__ void scatter_kernel(const int* __restrict__ row,
                               const int* __restrict__ col,
                               const float* __restrict__ ew) {
    int e = blockIdx.x * blockDim.x + threadIdx.x;
    if (e >= EE) return;
    int r = row[e], c = col[e];
    float w = (r == c) ? 0.f : ew[e];
    float wn = -g_deg[r] * w * g_deg[c];     // lambda_max=2 -> factor 1
    int pos = atomicAdd(&g_cur[c], 1);
    int2 p;
    p.x = r;
    p.y = __float_as_int(wn);
    g_pack[g_off[c] + pos] = p;
}

// ---------------- gather SPMM: out[n] = alpha * sum_e w*in[src] (- prev[n]) --
template <int F>
__global__ void spmm_gather(const float* __restrict__ in, float* __restrict__ out,
                            const float* __restrict__ prev, float alpha) {
    constexpr int WPN = F / 128;
    int gw = (blockIdx.x * blockDim.x + threadIdx.x) >> 5;
    int node = gw / WPN;
    int fc = gw % WPN;
    if (node >= NN) return;
    int lane = threadIdx.x & 31;
    int beg = g_off[node], end = g_off[node + 1];

    const float4* base = (const float4*)in + fc * 32 + lane;
    float4 acc0 = make_float4(0.f, 0.f, 0.f, 0.f);
    float4 acc1 = make_float4(0.f, 0.f, 0.f, 0.f);

    int i = beg;
    for (; i + 2 <= end; i += 2) {
        int2 p0 = g_pack[i];
        int2 p1 = g_pack[i + 1];
        float w0 = __int_as_float(p0.y);
        float w1 = __int_as_float(p1.y);
        float4 v0 = base[(size_t)p0.x * (F / 4)];
        float4 v1 = base[(size_t)p1.x * (F / 4)];
        acc0.x = fmaf(w0, v0.x, acc0.x); acc0.y = fmaf(w0, v0.y, acc0.y);
        acc0.z = fmaf(w0, v0.z, acc0.z); acc0.w = fmaf(w0, v0.w, acc0.w);
        acc1.x = fmaf(w1, v1.x, acc1.x); acc1.y = fmaf(w1, v1.y, acc1.y);
        acc1.z = fmaf(w1, v1.z, acc1.z); acc1.w = fmaf(w1, v1.w, acc1.w);
    }
    if (i < end) {
        int2 p0 = g_pack[i];
        float w0 = __int_as_float(p0.y);
        float4 v0 = base[(size_t)p0.x * (F / 4)];
        acc0.x = fmaf(w0, v0.x, acc0.x); acc0.y = fmaf(w0, v0.y, acc0.y);
        acc0.z = fmaf(w0, v0.z, acc0.z); acc0.w = fmaf(w0, v0.w, acc0.w);
    }
    float4 r;
    r.x = alpha * (acc0.x + acc1.x);
    r.y = alpha * (acc0.y + acc1.y);
    r.z = alpha * (acc0.z + acc1.z);
    r.w = alpha * (acc0.w + acc1.w);
    size_t oidx = (size_t)node * (F / 4) + fc * 32 + lane;
    if (prev) {
        float4 pv = ((const float4*)prev)[oidx];
        r.x -= pv.x; r.y -= pv.y; r.z -= pv.z; r.w -= pv.w;
    }
    ((float4*)out)[oidx] = r;
}

// ---------------- TF32 tensor-core GEMM -------------------------------------
// C[NPAD][FOUT] = sum_{chunk} A_chunk[NPAD][FIN] @ W_chunk[FIN][FOUT] + bias
__device__ __forceinline__ unsigned f2tf32(float f) {
    unsigned u;
    asm("cvt.rna.tf32.f32 %0, %1;" : "=r"(u) : "f"(f));
    return u;
}

#define AS_PITCH 36
#define BS_PITCH 132

template <int FIN, int FOUTT>
__global__ __launch_bounds__(256)
void gemm_tf32(const float* __restrict__ A, const float* __restrict__ W,
               const float* __restrict__ bias, float* __restrict__ C) {
    __shared__ unsigned As[128 * AS_PITCH];   // [row][k], pitch 36
    __shared__ unsigned Bs[32 * BS_PITCH];    // [k][n],   pitch 132

    const int tid = threadIdx.x;
    const int lane = tid & 31;
    const int wid = tid >> 5;
    const int warp_m = wid >> 2;        // 0..1
    const int warp_n = wid & 3;         // 0..3
    const int bm = blockIdx.x * 128;
    const int bn = blockIdx.y * 128;

    float acc[4][4][4];                 // [msub][nsub][frag]
#pragma unroll
    for (int i = 0; i < 4; i++)
#pragma unroll
        for (int j = 0; j < 4; j++)
#pragma unroll
            for (int q = 0; q < 4; q++) acc[i][j][q] = 0.f;

    // LDSM base address (per lane) for A fragments
    const unsigned asBase = __cvta_generic_to_shared(
        &As[(warp_m * 64 + (lane & 15)) * AS_PITCH + (lane >> 4) * 4]);

#pragma unroll 1
    for (int chunk = 0; chunk < 4; ++chunk) {
        const float* Ab = A + (size_t)chunk * NPAD * FIN;
        const float* Wb = W + (size_t)chunk * FIN * FOUTT;
#pragma unroll 1
        for (int k0 = 0; k0 < FIN; k0 += 32) {
            // load A tile 128x32 (convert to tf32 bits)
            {
                int m = tid >> 3;            // 0..31
                int kg = (tid & 7) * 4;      // 0..28
#pragma unroll
                for (int p = 0; p < 4; ++p) {
                    int mr = m + p * 32;
                    float4 v = *(const float4*)(Ab + (size_t)(bm + mr) * FIN + k0 + kg);
                    unsigned* d = &As[mr * AS_PITCH + kg];
                    d[0] = f2tf32(v.x); d[1] = f2tf32(v.y);
                    d[2] = f2tf32(v.z); d[3] = f2tf32(v.w);
                }
            }
            // load B tile 32x128
            {
                int k = tid >> 5;            // 0..7
                int n4 = (tid & 31) * 4;     // 0..124
#pragma unroll
                for (int p = 0; p < 4; ++p) {
                    int kr = k + p * 8;
                    float4 v = *(const float4*)(Wb + (size_t)(k0 + kr) * FOUTT + bn + n4);
                    unsigned* d = &Bs[kr * BS_PITCH + n4];
                    d[0] = f2tf32(v.x); d[1] = f2tf32(v.y);
                    d[2] = f2tf32(v.z); d[3] = f2tf32(v.w);
                }
            }
            __syncthreads();

#pragma unroll
            for (int k8 = 0; k8 < 4; ++k8) {
                unsigned a[4][4];
#pragma unroll
                for (int ms = 0; ms < 4; ++ms) {
                    unsigned addr = asBase + (ms * 16 * AS_PITCH + k8 * 8) * 4;
                    asm volatile(
                        "ldmatrix.sync.aligned.m8n8.x4.shared.b16 {%0,%1,%2,%3}, [%4];"
                        : "=r"(a[ms][0]), "=r"(a[ms][1]), "=r"(a[ms][2]), "=r"(a[ms][3])
                        : "r"(addr));
                }
                unsigned b0[4], b1[4];
                {
                    int bRow = k8 * 8 + (lane & 3);
                    int bCol = warp_n * 32 + (lane >> 2);
#pragma unroll
                    for (int ns = 0; ns < 4; ++ns) {
                        b0[ns] = Bs[bRow * BS_PITCH + bCol + ns * 8];
                        b1[ns] = Bs[(bRow + 4) * BS_PITCH + bCol + ns * 8];
                    }
                }
#pragma unroll
                for (int ms = 0; ms < 4; ++ms)
#pragma unroll
                    for (int ns = 0; ns < 4; ++ns) {
                        asm volatile(
                            "mma.sync.aligned.m16n8k8.row.col.f32.tf32.tf32.f32 "
                            "{%0,%1,%2,%3}, {%4,%5,%6,%7}, {%8,%9}, {%0,%1,%2,%3};"
                            : "+f"(acc[ms][ns][0]), "+f"(acc[ms][ns][1]),
                              "+f"(acc[ms][ns][2]), "+f"(acc[ms][ns][3])
                            : "r"(a[ms][0]), "r"(a[ms][1]), "r"(a[ms][2]), "r"(a[ms][3]),
                              "r"(b0[ns]), "r"(b1[ns]));
                    }
            }
            __syncthreads();
        }
    }

    // epilogue: D + bias -> C  (rows padded; no guards)
#pragma unroll
    for (int ms = 0; ms < 4; ++ms) {
        int r0 = bm + warp_m * 64 + ms * 16 + (lane >> 2);
#pragma unroll
        for (int ns = 0; ns < 4; ++ns) {
            int cc = bn + warp_n * 32 + ns * 8 + 2 * (lane & 3);
            float2 v0, v1;
            v0.x = acc[ms][ns][0] + bias[cc + 0];
            v0.y = acc[ms][ns][1] + bias[cc + 1];
            v1.x = acc[ms][ns][2] + bias[cc + 0];
            v1.y = acc[ms][ns][3] + bias[cc + 1];
            *(float2*)(C + (size_t)r0 * FOUTT + cc) = v0;
            *(float2*)(C + (size_t)(r0 + 8) * FOUTT + cc) = v1;
        }
    }
}

// ---------------- BN (training) over node axis, relu fused ------------------
template <int F>
__global__ void stats_kernel(const float* __restrict__ X) {
    int col = threadIdx.x & (F - 1);
    int ro = threadIdx.x / F;
    int rstep = 256 / F;
    int r0 = blockIdx.x * 128 + ro;
    int rend = blockIdx.x * 128 + 128;
    if (rend > NN) rend = NN;
    float s = 0.f, s2 = 0.f;
    for (int r = r0; r < rend; r += rstep) {
        float v = X[(size_t)r * F + col];
        v = v > 0.f ? v : 0.f;
        s += v;
        s2 = fmaf(v, v, s2);
    }
    atomicAdd(&g_stats[col], s);
    atomicAdd(&g_stats[F + col], s2);
}

__global__ void scaleshift_kernel(const float* __restrict__ gamma,
                                  const float* __restrict__ beta, int F) {
    int c = threadIdx.x;
    if (c >= F) return;
    float m = g_stats[c] / (float)NN;
    float v = g_stats[F + c] / (float)NN - m * m;
    float inv = rsqrtf(v + 1e-5f);
    float sc = gamma[c] * inv;
    g_scale[c] = sc;
    g_shift[c] = beta[c] - m * sc;
}

template <int F>
__global__ void bnapply_kernel(const float* __restrict__ x, float* __restrict__ y, int n) {
    int i = blockIdx.x * blockDim.x + threadIdx.x;
    if (i >= n) return;
    int c = i & (F - 1);
    float v = x[i];
    v = v > 0.f ? v : 0.f;
    y[i] = fmaf(v, g_scale[c], g_shift[c]);
}

// ---------------- final linear: out = h2 @ Wlin^T + blin --------------------
__global__ void final_kernel(const float* __restrict__ h, const float* __restrict__ Wl,
                             const float* __restrict__ bl, float* __restrict__ out) {
    int idx = blockIdx.x * blockDim.x + threadIdx.x;
    int n = idx >> 4;
    int o = idx & 15;
    if (n >= NN || o >= 10) return;
    const float* hr = h + (size_t)n * F2;
    const float* wr = Wl + o * F2;
    float s = bl[o];
#pragma unroll 8
    for (int c = 0; c < F2; ++c) s = fmaf(hr[c], wr[c], s);
    out[n * 10 + o] = s;
}

// ---------------- launch ----------------------------------------------------
extern "C" void kernel_launch(void* const* d_in, const int* in_sizes, int n_in,
                              void* d_out, int out_size) {
    const float* x      = (const float*)d_in[0];
    const int*   ei     = (const int*)d_in[1];
    const float* ew     = (const float*)d_in[2];
    const float* W1     = (const float*)d_in[3];
    const float* b1     = (const float*)d_in[4];
    const float* W2     = (const float*)d_in[5];
    const float* b2     = (const float*)d_in[6];
    const float* gamma1 = (const float*)d_in[7];
    const float* beta1  = (const float*)d_in[8];
    const float* gamma2 = (const float*)d_in[9];
    const float* beta2  = (const float*)d_in[10];
    const float* Wlin   = (const float*)d_in[11];
    const float* blin   = (const float*)d_in[12];
    float* out = (float*)d_out;

    const int* row = ei;
    const int* col = ei + EE;

    float *deg, *TxA, *TxB, *out1, *out2, *h2, *stats;
    int *cnt, *cur;
    cudaGetSymbolAddress((void**)&deg,   g_deg);
    cudaGetSymbolAddress((void**)&cnt,   g_cnt);
    cudaGetSymbolAddress((void**)&cur,   g_cur);
    cudaGetSymbolAddress((void**)&TxA,   g_TxA);
    cudaGetSymbolAddress((void**)&TxB,   g_TxB);
    cudaGetSymbolAddress((void**)&out1,  g_out1);
    cudaGetSymbolAddress((void**)&out2,  g_out2);
    cudaGetSymbolAddress((void**)&h2,    g_h2);
    cudaGetSymbolAddress((void**)&stats, g_stats);

    const int EB = (EE + 255) / 256;

    // ---- normalization + CSR build ----
    cudaMemsetAsync(deg, 0, NPAD * sizeof(float));
    cudaMemsetAsync(cnt, 0, NPAD * sizeof(int));
    cudaMemsetAsync(cur, 0, NPAD * sizeof(int));
    cudaMemsetAsync(stats, 0, 2 * F1 * sizeof(float));

    deg_cnt_kernel<<<EB, 256>>>(row, col, ew);
    dis_kernel<<<(NN + 255) / 256, 256>>>();
    scan_kernel<<<1, 1024>>>();
    scatter_kernel<<<EB, 256>>>(row, col, ew);

    cudaMemcpyAsync(TxA, x, (size_t)NN * F0 * sizeof(float), cudaMemcpyDeviceToDevice);

    // ---- layer 1 ----
    float* A0 = TxA;
    float* A1 = TxA + (size_t)NPAD * F0;
    float* A2 = TxA + (size_t)2 * NPAD * F0;
    float* A3 = TxA + (size_t)3 * NPAD * F0;
    const int GB0 = (NN * (F0 / 128) * 32 + 255) / 256;
    spmm_gather<F0><<<GB0, 256>>>(A0, A1, nullptr, 1.f);
    spmm_gather<F0><<<GB0, 256>>>(A1, A2, A0, 2.f);
    spmm_gather<F0><<<GB0, 256>>>(A2, A3, A1, 2.f);

    gemm_tf32<F0, F1><<<dim3(NPAD / 128, F1 / 128), 256>>>(TxA, W1, b1, out1);

    stats_kernel<F1><<<157, 256>>>(out1);
    scaleshift_kernel<<<1, 256>>>(gamma1, beta1, F1);
    bnapply_kernel<F1><<<(NN * F1 + 255) / 256, 256>>>(out1, TxB, NN * F1);

    // ---- layer 2 ----
    float* B0 = TxB;
    float* B1 = TxB + (size_t)NPAD * F1;
    float* B2 = TxB + (size_t)2 * NPAD * F1;
    float* B3 = TxB + (size_t)3 * NPAD * F1;
    const int GB1 = (NN * (F1 / 128) * 32 + 255) / 256;
    spmm_gather<F1><<<GB1, 256>>>(B0, B1, nullptr, 1.f);
    spmm_gather<F1><<<GB1, 256>>>(B1, B2, B0, 2.f);
    spmm_gather<F1><<<GB1, 256>>>(B2, B3, B1, 2.f);

    gemm_tf32<F1, F2><<<dim3(NPAD / 128, F2 / 128), 256>>>(TxB, W2, b2, out2);

    cudaMemsetAsync(stats, 0, 2 * F1 * sizeof(float));
    stats_kernel<F2><<<157, 256>>>(out2);
    scaleshift_kernel<<<1, 128>>>(gamma2, beta2, F2);
    bnapply_kernel<F2><<<(NN * F2 + 255) / 256, 256>>>(out2, h2, NN * F2);

    // ---- final linear ----
    final_kernel<<<(NN * 16 + 255) / 256, 256>>>(h2, Wlin, blin, out);
}

// round 5
// speedup vs baseline: 3.2045x; 1.3601x over previous
#include <cuda_runtime.h>
#include <cuda_bf16.h>
#include <cstdint>

// Problem constants
#define NN   20000
#define EE   640000
#define F0   128
#define F1   256
#define F2   128
#define NPAD 20096   // 157 * 128

// ---------------- scratch (device globals, zero at module load) -------------
__device__ __align__(16) float g_deg[NPAD];
__device__ __align__(16) int   g_cnt[NPAD];
__device__ __align__(16) int   g_cur[NPAD];
__device__ __align__(16) int   g_off[NN + 1];
__device__ __align__(16) int2  g_pack[EE];            // (src_row, w_norm) by dst
__device__ __align__(16) float g_TxA[4 * NPAD * F0];  // layer1 Cheb stack + layer2 temps
__device__ __align__(16) float g_out1[NPAD * F1];
__device__ __align__(16) float g_Ck[4 * NPAD * F2];   // layer2 Horner coefficients
__device__ __align__(16) float g_out2[NPAD * F2];
__device__ __align__(16) float g_W2c[4 * F1 * F2];    // precombined layer2 weights
__device__ __align__(16) float g_stats[2 * F1];
__device__ __align__(16) float g_scale[F1];
__device__ __align__(16) float g_shift[F1];

// ---------------- CSR build --------------------------------------------------
__global__ void deg_cnt_kernel(const int* __restrict__ row,
                               const int* __restrict__ col,
                               const float* __restrict__ ew) {
    int e = blockIdx.x * blockDim.x + threadIdx.x;
    if (e >= EE) return;
    int r = row[e], c = col[e];
    float w = (r == c) ? 0.f : ew[e];
    if (w != 0.f) atomicAdd(&g_deg[r], w);
    atomicAdd(&g_cnt[c], 1);
}

// fused: dis = rsqrt(deg), then exclusive scan of counts -> offsets
__global__ void scan_dis_kernel() {
    int tid = threadIdx.x;
    for (int i = tid; i < NN; i += 1024) {
        float d = g_deg[i];
        g_deg[i] = (d > 0.f) ? rsqrtf(d) : 0.f;
    }
    const int PER = 20;   // 1024*20 >= NN+1
    int base = tid * PER;
    int v[PER];
    int s = 0;
#pragma unroll
    for (int j = 0; j < PER; j++) {
        int idx = base + j;
        int t = (idx < NN) ? g_cnt[idx] : 0;
        v[j] = t;
        s += t;
    }
    int lane = tid & 31, warp = tid >> 5;
    int p = s;
#pragma unroll
    for (int o = 1; o < 32; o <<= 1) {
        int t = __shfl_up_sync(0xffffffffu, p, o);
        if (lane >= o) p += t;
    }
    __shared__ int wsum[32];
    if (lane == 31) wsum[warp] = p;
    __syncthreads();
    if (warp == 0) {
        int q = wsum[lane];
#pragma unroll
        for (int o = 1; o < 32; o <<= 1) {
            int t = __shfl_up_sync(0xffffffffu, q, o);
            if (lane >= o) q += t;
        }
        wsum[lane] = q;
    }
    __syncthreads();
    int run = p - s + (warp ? wsum[warp - 1] : 0);
#pragma unroll
    for (int j = 0; j < PER; j++) {
        int idx = base + j;
        if (idx <= NN) g_off[idx] = run;
        run += v[j];
    }
}

__global__ void scatter_kernel(const int* __restrict__ row,
                               const int* __restrict__ col,
                               const float* __restrict__ ew) {
    int e = blockIdx.x * blockDim.x + threadIdx.x;
    if (e >= EE) return;
    int r = row[e], c = col[e];
    float w = (r == c) ? 0.f : ew[e];
    float wn = -g_deg[r] * w * g_deg[c];
    int pos = atomicAdd(&g_cur[c], 1);
    int2 p;
    p.x = r;
    p.y = __float_as_int(wn);
    g_pack[g_off[c] + pos] = p;
}

// ---- gather SPMM (F=128): out = alpha*(L@in) - sub + add --------------------
__global__ void spmm_gather(const float* __restrict__ in, float* __restrict__ out,
                            const float* __restrict__ sub,
                            const float* __restrict__ add, float alpha) {
    int node = (blockIdx.x * blockDim.x + threadIdx.x) >> 5;
    if (node >= NN) return;
    int lane = threadIdx.x & 31;
    int beg = g_off[node], end = g_off[node + 1];

    const float4* base = (const float4*)in + lane;
    float4 acc0 = make_float4(0.f, 0.f, 0.f, 0.f);
    float4 acc1 = make_float4(0.f, 0.f, 0.f, 0.f);

    int i = beg;
    for (; i + 4 <= end; i += 4) {
        int2 p0 = g_pack[i], p1 = g_pack[i + 1], p2 = g_pack[i + 2], p3 = g_pack[i + 3];
        float w0 = __int_as_float(p0.y), w1 = __int_as_float(p1.y);
        float w2 = __int_as_float(p2.y), w3 = __int_as_float(p3.y);
        float4 v0 = base[(size_t)p0.x * 32];
        float4 v1 = base[(size_t)p1.x * 32];
        float4 v2 = base[(size_t)p2.x * 32];
        float4 v3 = base[(size_t)p3.x * 32];
        acc0.x = fmaf(w0, v0.x, acc0.x); acc0.y = fmaf(w0, v0.y, acc0.y);
        acc0.z = fmaf(w0, v0.z, acc0.z); acc0.w = fmaf(w0, v0.w, acc0.w);
        acc1.x = fmaf(w1, v1.x, acc1.x); acc1.y = fmaf(w1, v1.y, acc1.y);
        acc1.z = fmaf(w1, v1.z, acc1.z); acc1.w = fmaf(w1, v1.w, acc1.w);
        acc0.x = fmaf(w2, v2.x, acc0.x); acc0.y = fmaf(w2, v2.y, acc0.y);
        acc0.z = fmaf(w2, v2.z, acc0.z); acc0.w = fmaf(w2, v2.w, acc0.w);
        acc1.x = fmaf(w3, v3.x, acc1.x); acc1.y = fmaf(w3, v3.y, acc1.y);
        acc1.z = fmaf(w3, v3.z, acc1.z); acc1.w = fmaf(w3, v3.w, acc1.w);
    }
    for (; i < end; ++i) {
        int2 p0 = g_pack[i];
        float w0 = __int_as_float(p0.y);
        float4 v0 = base[(size_t)p0.x * 32];
        acc0.x = fmaf(w0, v0.x, acc0.x); acc0.y = fmaf(w0, v0.y, acc0.y);
        acc0.z = fmaf(w0, v0.z, acc0.z); acc0.w = fmaf(w0, v0.w, acc0.w);
    }
    float4 r;
    r.x = alpha * (acc0.x + acc1.x);
    r.y = alpha * (acc0.y + acc1.y);
    r.z = alpha * (acc0.z + acc1.z);
    r.w = alpha * (acc0.w + acc1.w);
    size_t oidx = (size_t)node * 32 + lane;
    if (add) {
        float4 av = ((const float4*)add)[oidx];
        r.x += av.x; r.y += av.y; r.z += av.z; r.w += av.w;
    }
    if (sub) {
        float4 sv = ((const float4*)sub)[oidx];
        r.x -= sv.x; r.y -= sv.y; r.z -= sv.z; r.w -= sv.w;
    }
    ((float4*)out)[oidx] = r;
}

// ---------------- TF32 helpers ----------------------------------------------
__device__ __forceinline__ unsigned f2tf32(float f) {
    unsigned u;
    asm("cvt.rna.tf32.f32 %0, %1;" : "=r"(u) : "f"(f));
    return u;
}
#define AS_PITCH 36
#define BS_PITCH 132

// ---- GEMM1: out1 = sum_chunk TxA_chunk[NPAD][128] @ W1_chunk[128][256] + b1 -
__global__ __launch_bounds__(256)
void gemm1_tf32(const float* __restrict__ A, const float* __restrict__ W,
                const float* __restrict__ bias, float* __restrict__ C) {
    const int FIN = F0, FOUTT = F1;
    __shared__ unsigned As[128 * AS_PITCH];
    __shared__ unsigned Bs[32 * BS_PITCH];

    const int tid = threadIdx.x;
    const int lane = tid & 31;
    const int wid = tid >> 5;
    const int warp_m = wid >> 2;
    const int warp_n = wid & 3;
    const int bm = blockIdx.x * 128;
    const int bn = blockIdx.y * 128;

    float acc[4][4][4];
#pragma unroll
    for (int i = 0; i < 4; i++)
#pragma unroll
        for (int j = 0; j < 4; j++)
#pragma unroll
            for (int q = 0; q < 4; q++) acc[i][j][q] = 0.f;

    const unsigned asBase = __cvta_generic_to_shared(
        &As[(warp_m * 64 + (lane & 15)) * AS_PITCH + (lane >> 4) * 4]);

#pragma unroll 1
    for (int chunk = 0; chunk < 4; ++chunk) {
        const float* Ab = A + (size_t)chunk * NPAD * FIN;
        const float* Wb = W + (size_t)chunk * FIN * FOUTT;
#pragma unroll 1
        for (int k0 = 0; k0 < FIN; k0 += 32) {
            {
                int m = tid >> 3;
                int kg = (tid & 7) * 4;
#pragma unroll
                for (int p = 0; p < 4; ++p) {
                    int mr = m + p * 32;
                    float4 v = *(const float4*)(Ab + (size_t)(bm + mr) * FIN + k0 + kg);
                    unsigned* d = &As[mr * AS_PITCH + kg];
                    d[0] = f2tf32(v.x); d[1] = f2tf32(v.y);
                    d[2] = f2tf32(v.z); d[3] = f2tf32(v.w);
                }
            }
            {
                int k = tid >> 5;
                int n4 = (tid & 31) * 4;
#pragma unroll
                for (int p = 0; p < 4; ++p) {
                    int kr = k + p * 8;
                    float4 v = *(const float4*)(Wb + (size_t)(k0 + kr) * FOUTT + bn + n4);
                    unsigned* d = &Bs[kr * BS_PITCH + n4];
                    d[0] = f2tf32(v.x); d[1] = f2tf32(v.y);
                    d[2] = f2tf32(v.z); d[3] = f2tf32(v.w);
                }
            }
            __syncthreads();
#pragma unroll
            for (int k8 = 0; k8 < 4; ++k8) {
                unsigned a[4][4];
#pragma unroll
                for (int ms = 0; ms < 4; ++ms) {
                    unsigned addr = asBase + (ms * 16 * AS_PITCH + k8 * 8) * 4;
                    asm volatile(
                        "ldmatrix.sync.aligned.m8n8.x4.shared.b16 {%0,%1,%2,%3}, [%4];"
                        : "=r"(a[ms][0]), "=r"(a[ms][1]), "=r"(a[ms][2]), "=r"(a[ms][3])
                        : "r"(addr));
                }
                unsigned b0[4], b1[4];
                {
                    int bRow = k8 * 8 + (lane & 3);
                    int bCol = warp_n * 32 + (lane >> 2);
#pragma unroll
                    for (int ns = 0; ns < 4; ++ns) {
                        b0[ns] = Bs[bRow * BS_PITCH + bCol + ns * 8];
                        b1[ns] = Bs[(bRow + 4) * BS_PITCH + bCol + ns * 8];
                    }
                }
#pragma unroll
                for (int ms = 0; ms < 4; ++ms)
#pragma unroll
                    for (int ns = 0; ns < 4; ++ns) {
                        asm volatile(
                            "mma.sync.aligned.m16n8k8.row.col.f32.tf32.tf32.f32 "
                            "{%0,%1,%2,%3}, {%4,%5,%6,%7}, {%8,%9}, {%0,%1,%2,%3};"
                            : "+f"(acc[ms][ns][0]), "+f"(acc[ms][ns][1]),
                              "+f"(acc[ms][ns][2]), "+f"(acc[ms][ns][3])
                            : "r"(a[ms][0]), "r"(a[ms][1]), "r"(a[ms][2]), "r"(a[ms][3]),
                              "r"(b0[ns]), "r"(b1[ns]));
                    }
            }
            __syncthreads();
        }
    }
#pragma unroll
    for (int ms = 0; ms < 4; ++ms) {
        int r0 = bm + warp_m * 64 + ms * 16 + (lane >> 2);
#pragma unroll
        for (int ns = 0; ns < 4; ++ns) {
            int cc = bn + warp_n * 32 + ns * 8 + 2 * (lane & 3);
            float2 v0, v1;
            v0.x = acc[ms][ns][0] + bias[cc + 0];
            v0.y = acc[ms][ns][1] + bias[cc + 1];
            v1.x = acc[ms][ns][2] + bias[cc + 0];
            v1.y = acc[ms][ns][3] + bias[cc + 1];
            *(float2*)(C + (size_t)r0 * FOUTT + cc) = v0;
            *(float2*)(C + (size_t)(r0 + 8) * FOUTT + cc) = v1;
        }
    }
}

// ---- weight precombine for layer-2 Horner form ------------------------------
__global__ void wcomb_kernel(const float* __restrict__ W2) {
    int i = blockIdx.x * blockDim.x + threadIdx.x;
    const int SZ = F1 * F2;
    if (i >= SZ) return;
    float w0 = W2[i], w1 = W2[SZ + i], w2 = W2[2 * SZ + i], w3 = W2[3 * SZ + i];
    g_W2c[i]          = w0 - w2;          // C0 weights
    g_W2c[SZ + i]     = w1 - 3.f * w3;    // C1
    g_W2c[2 * SZ + i] = 2.f * w2;         // C2
    g_W2c[3 * SZ + i] = 4.f * w3;         // C3
}

// ---- GEMM2: C_k = BNrelu(out1) @ W2c_k (+ b2 for k=0), k = blockIdx.y -------
__global__ __launch_bounds__(256)
void gemm2_tf32(const float* __restrict__ A, const float* __restrict__ bias) {
    const int FIN = F1, FOUTT = F2;
    __shared__ unsigned As[128 * AS_PITCH];
    __shared__ unsigned Bs[32 * BS_PITCH];

    const int tid = threadIdx.x;
    const int lane = tid & 31;
    const int wid = tid >> 5;
    const int warp_m = wid >> 2;
    const int warp_n = wid & 3;
    const int bm = blockIdx.x * 128;
    const int kblk = blockIdx.y;
    const float* Wb = g_W2c + (size_t)kblk * FIN * FOUTT;
    float* C = g_Ck + (size_t)kblk * NPAD * FOUTT;

    float acc[4][4][4];
#pragma unroll
    for (int i = 0; i < 4; i++)
#pragma unroll
        for (int j = 0; j < 4; j++)
#pragma unroll
            for (int q = 0; q < 4; q++) acc[i][j][q] = 0.f;

    const unsigned asBase = __cvta_generic_to_shared(
        &As[(warp_m * 64 + (lane & 15)) * AS_PITCH + (lane >> 4) * 4]);

#pragma unroll 1
    for (int k0 = 0; k0 < FIN; k0 += 32) {
        {
            int m = tid >> 3;
            int kg = (tid & 7) * 4;
            float4 sc = *(const float4*)&g_scale[k0 + kg];
            float4 sh = *(const float4*)&g_shift[k0 + kg];
#pragma unroll
            for (int p = 0; p < 4; ++p) {
                int mr = m + p * 32;
                float4 v = *(const float4*)(A + (size_t)(bm + mr) * FIN + k0 + kg);
                v.x = fmaf(fmaxf(v.x, 0.f), sc.x, sh.x);
                v.y = fmaf(fmaxf(v.y, 0.f), sc.y, sh.y);
                v.z = fmaf(fmaxf(v.z, 0.f), sc.z, sh.z);
                v.w = fmaf(fmaxf(v.w, 0.f), sc.w, sh.w);
                unsigned* d = &As[mr * AS_PITCH + kg];
                d[0] = f2tf32(v.x); d[1] = f2tf32(v.y);
                d[2] = f2tf32(v.z); d[3] = f2tf32(v.w);
            }
        }
        {
            int k = tid >> 5;
            int n4 = (tid & 31) * 4;
#pragma unroll
            for (int p = 0; p < 4; ++p) {
                int kr = k + p * 8;
                float4 v = *(const float4*)(Wb + (size_t)(k0 + kr) * FOUTT + n4);
                unsigned* d = &Bs[kr * BS_PITCH + n4];
                d[0] = f2tf32(v.x); d[1] = f2tf32(v.y);
                d[2] = f2tf32(v.z); d[3] = f2tf32(v.w);
            }
        }
        __syncthreads();
#pragma unroll
        for (int k8 = 0; k8 < 4; ++k8) {
            unsigned a[4][4];
#pragma unroll
            for (int ms = 0; ms < 4; ++ms) {
                unsigned addr = asBase + (ms * 16 * AS_PITCH + k8 * 8) * 4;
                asm volatile(
                    "ldmatrix.sync.aligned.m8n8.x4.shared.b16 {%0,%1,%2,%3}, [%4];"
                    : "=r"(a[ms][0]), "=r"(a[ms][1]), "=r"(a[ms][2]), "=r"(a[ms][3])
                    : "r"(addr));
            }
            unsigned b0[4], b1[4];
            {
                int bRow = k8 * 8 + (lane & 3);
                int bCol = warp_n * 32 + (lane >> 2);
#pragma unroll
                for (int ns = 0; ns < 4; ++ns) {
                    b0[ns] = Bs[bRow * BS_PITCH + bCol + ns * 8];
                    b1[ns] = Bs[(bRow + 4) * BS_PITCH + bCol + ns * 8];
                }
            }
#pragma unroll
            for (int ms = 0; ms < 4; ++ms)
#pragma unroll
                for (int ns = 0; ns < 4; ++ns) {
                    asm volatile(
                        "mma.sync.aligned.m16n8k8.row.col.f32.tf32.tf32.f32 "
                        "{%0,%1,%2,%3}, {%4,%5,%6,%7}, {%8,%9}, {%0,%1,%2,%3};"
                        : "+f"(acc[ms][ns][0]), "+f"(acc[ms][ns][1]),
                          "+f"(acc[ms][ns][2]), "+f"(acc[ms][ns][3])
                        : "r"(a[ms][0]), "r"(a[ms][1]), "r"(a[ms][2]), "r"(a[ms][3]),
                          "r"(b0[ns]), "r"(b1[ns]));
                }
        }
        __syncthreads();
    }
    bool addb = (kblk == 0);
#pragma unroll
    for (int ms = 0; ms < 4; ++ms) {
        int r0 = bm + warp_m * 64 + ms * 16 + (lane >> 2);
#pragma unroll
        for (int ns = 0; ns < 4; ++ns) {
            int cc = warp_n * 32 + ns * 8 + 2 * (lane & 3);
            float bx = addb ? bias[cc + 0] : 0.f;
            float by = addb ? bias[cc + 1] : 0.f;
            float2 v0, v1;
            v0.x = acc[ms][ns][0] + bx;
            v0.y = acc[ms][ns][1] + by;
            v1.x = acc[ms][ns][2] + bx;
            v1.y = acc[ms][ns][3] + by;
            *(float2*)(C + (size_t)r0 * FOUTT + cc) = v0;
            *(float2*)(C + (size_t)(r0 + 8) * FOUTT + cc) = v1;
        }
    }
}

// ---------------- BN stats (relu fused) --------------------------------------
template <int F>
__global__ void stats_kernel(const float* __restrict__ X) {
    int col = threadIdx.x & (F - 1);
    int ro = threadIdx.x / F;
    int rstep = 256 / F;
    int r0 = blockIdx.x * 128 + ro;
    int rend = blockIdx.x * 128 + 128;
    if (rend > NN) rend = NN;
    float s = 0.f, s2 = 0.f;
    for (int r = r0; r < rend; r += rstep) {
        float v = X[(size_t)r * F + col];
        v = v > 0.f ? v : 0.f;
        s += v;
        s2 = fmaf(v, v, s2);
    }
    atomicAdd(&g_stats[col], s);
    atomicAdd(&g_stats[F + col], s2);
}

__global__ void scaleshift_kernel(const float* __restrict__ gamma,
                                  const float* __restrict__ beta, int F) {
    int c = threadIdx.x;
    if (c >= F) return;
    float m = g_stats[c] / (float)NN;
    float v = g_stats[F + c] / (float)NN - m * m;
    float inv = rsqrtf(v + 1e-5f);
    float sc = gamma[c] * inv;
    g_scale[c] = sc;
    g_shift[c] = beta[c] - m * sc;
}

// ---- final: out = BNrelu(out2) @ Wlin^T + blin, warp per node ---------------
__global__ void final_kernel(const float* __restrict__ h, const float* __restrict__ Wl,
                             const float* __restrict__ bl, float* __restrict__ out) {
    int node = (blockIdx.x * blockDim.x + threadIdx.x) >> 5;
    if (node >= NN) return;
    int lane = threadIdx.x & 31;
    float4 v = ((const float4*)(h + (size_t)node * F2))[lane];
    int c = lane * 4;
    float h0 = fmaf(fmaxf(v.x, 0.f), g_scale[c + 0], g_shift[c + 0]);
    float h1 = fmaf(fmaxf(v.y, 0.f), g_scale[c + 1], g_shift[c + 1]);
    float h2 = fmaf(fmaxf(v.z, 0.f), g_scale[c + 2], g_shift[c + 2]);
    float h3 = fmaf(fmaxf(v.w, 0.f), g_scale[c + 3], g_shift[c + 3]);
#pragma unroll
    for (int o = 0; o < 10; ++o) {
        float4 w = ((const float4*)(Wl + o * F2))[lane];
        float p = h0 * w.x + h1 * w.y + h2 * w.z + h3 * w.w;
        p += __shfl_xor_sync(0xffffffffu, p, 16);
        p += __shfl_xor_sync(0xffffffffu, p, 8);
        p += __shfl_xor_sync(0xffffffffu, p, 4);
        p += __shfl_xor_sync(0xffffffffu, p, 2);
        p += __shfl_xor_sync(0xffffffffu, p, 1);
        if (lane == 0) out[node * 10 + o] = p + bl[o];
    }
}

// ---------------- launch ------------------------------------------------------
extern "C" void kernel_launch(void* const* d_in, const int* in_sizes, int n_in,
                              void* d_out, int out_size) {
    const float* x      = (const float*)d_in[0];
    const int*   ei     = (const int*)d_in[1];
    const float* ew     = (const float*)d_in[2];
    const float* W1     = (const float*)d_in[3];
    const float* b1     = (const float*)d_in[4];
    const float* W2     = (const float*)d_in[5];
    const float* b2     = (const float*)d_in[6];
    const float* gamma1 = (const float*)d_in[7];
    const float* beta1  = (const float*)d_in[8];
    const float* gamma2 = (const float*)d_in[9];
    const float* beta2  = (const float*)d_in[10];
    const float* Wlin   = (const float*)d_in[11];
    const float* blin   = (const float*)d_in[12];
    float* out = (float*)d_out;

    const int* row = ei;
    const int* col = ei + EE;

    float *deg, *TxA, *out1, *Ck, *out2, *stats;
    int *cnt, *cur;
    cudaGetSymbolAddress((void**)&deg,   g_deg);
    cudaGetSymbolAddress((void**)&cnt,   g_cnt);
    cudaGetSymbolAddress((void**)&cur,   g_cur);
    cudaGetSymbolAddress((void**)&TxA,   g_TxA);
    cudaGetSymbolAddress((void**)&out1,  g_out1);
    cudaGetSymbolAddress((void**)&Ck,    g_Ck);
    cudaGetSymbolAddress((void**)&out2,  g_out2);
    cudaGetSymbolAddress((void**)&stats, g_stats);

    const int EB = (EE + 255) / 256;
    const int SB = (NN * 32 + 255) / 256;   // warp-per-node grids

    // ---- CSR build ----
    cudaMemsetAsync(deg, 0, NPAD * sizeof(float));
    cudaMemsetAsync(cnt, 0, NPAD * sizeof(int));
    cudaMemsetAsync(cur, 0, NPAD * sizeof(int));
    cudaMemsetAsync(stats, 0, 2 * F1 * sizeof(float));

    deg_cnt_kernel<<<EB, 256>>>(row, col, ew);
    scan_dis_kernel<<<1, 1024>>>();
    scatter_kernel<<<EB, 256>>>(row, col, ew);

    cudaMemcpyAsync(TxA, x, (size_t)NN * F0 * sizeof(float), cudaMemcpyDeviceToDevice);

    // ---- layer 1: Chebyshev recursion at F=128 ----
    float* A0 = TxA;
    float* A1 = TxA + (size_t)NPAD * F0;
    float* A2 = TxA + (size_t)2 * NPAD * F0;
    float* A3 = TxA + (size_t)3 * NPAD * F0;
    spmm_gather<<<SB, 256>>>(A0, A1, nullptr, nullptr, 1.f);
    spmm_gather<<<SB, 256>>>(A1, A2, A0, nullptr, 2.f);
    spmm_gather<<<SB, 256>>>(A2, A3, A1, nullptr, 2.f);

    gemm1_tf32<<<dim3(NPAD / 128, 2), 256>>>(TxA, W1, b1, out1);

    stats_kernel<F1><<<157, 256>>>(out1);
    scaleshift_kernel<<<1, 256>>>(gamma1, beta1, F1);
    cudaMemsetAsync(stats, 0, 2 * F1 * sizeof(float));   // for stats2 later

    // ---- layer 2: Horner form ----
    wcomb_kernel<<<(F1 * F2 + 255) / 256, 256>>>(W2);
    gemm2_tf32<<<dim3(NPAD / 128, 4), 256>>>(out1, b2);   // C_k = BNrelu(out1)@W2c_k

    float* C0 = Ck;
    float* C1 = Ck + (size_t)NPAD * F2;
    float* C2 = Ck + (size_t)2 * NPAD * F2;
    float* C3 = Ck + (size_t)3 * NPAD * F2;
    float* t1 = TxA;                       // reuse layer1 scratch
    float* t2 = TxA + (size_t)NPAD * F0;
    spmm_gather<<<SB, 256>>>(C3, t1, nullptr, C2, 1.f);   // t1 = L C3 + C2
    spmm_gather<<<SB, 256>>>(t1, t2, nullptr, C1, 1.f);   // t2 = L t1 + C1
    spmm_gather<<<SB, 256>>>(t2, out2, nullptr, C0, 1.f); // out2 = L t2 + C0

    stats_kernel<F2><<<157, 256>>>(out2);
    scaleshift_kernel<<<1, 128>>>(gamma2, beta2, F2);

    final_kernel<<<SB, 256>>>(out2, Wlin, blin, out);
}